// round 17
// baseline (speedup 1.0000x reference)
#include <cuda_runtime.h>
#include <cuda_bf16.h>
#include <cuda_fp16.h>

// Problem constants (fixed shapes for GAT_68762426409265)
#define NN  100000          // nodes
#define FIN 256             // input features
#define HID 64              // hidden
#define NC  40              // classes
#define EE  1600000         // edges (without self loops)
#define ET  (EE + NN)       // edges + self loops

// ---------------- device scratch (static, no allocation) ----------------
__device__ unsigned g_h1h[(size_t)NN * (HID / 2)];  // layer1 projection, packed half2
__device__ unsigned g_h2h[(size_t)NN * (NC / 2)];   // layer2 projection, packed half2
__device__ float    g_s1[NN];
__device__ float    g_d1[NN];
__device__ float    g_s2[NN];
__device__ float    g_d2[NN];
__device__ int      g_cnt[NN];
__device__ int      g_scan[NN];
__device__ int      g_rowptr[NN + 1];
__device__ int      g_cursor[NN];
__device__ int      g_bsum[128];
__device__ int2     g_edge[ET];                     // packed {src, ew-bits}
__device__ unsigned g_W1h[(FIN / 2) * HID];         // W1 as half2 pairs along k

// ---------------- small asm helpers ----------------
__device__ __forceinline__ unsigned pkh2(float lo, float hi) {
    unsigned r;
    asm("cvt.rn.f16x2.f32 %0, %1, %2;" : "=r"(r) : "f"(hi), "f"(lo));
    return r;
}
__device__ __forceinline__ float2 uph2(unsigned u) {
    __half2 h = *reinterpret_cast<__half2*>(&u);
    return __half22float2(h);
}
// m16n8k16 fp16 MMA, fp32 accumulate
__device__ __forceinline__ void mma_f16(float* c, const unsigned* a, const unsigned* b) {
    asm volatile("mma.sync.aligned.m16n8k16.row.col.f32.f16.f16.f32 "
                 "{%0,%1,%2,%3}, {%4,%5,%6,%7}, {%8,%9}, {%0,%1,%2,%3};"
                 : "+f"(c[0]), "+f"(c[1]), "+f"(c[2]), "+f"(c[3])
                 : "r"(a[0]), "r"(a[1]), "r"(a[2]), "r"(a[3]),
                   "r"(b[0]), "r"(b[1]));
}
__device__ __forceinline__ void cpa16(void* dst_smem, const void* src, bool pred) {
    unsigned d = (unsigned)__cvta_generic_to_shared(dst_smem);
    int sz = pred ? 16 : 0;   // src-size 0 => zero-fill
    asm volatile("cp.async.cg.shared.global [%0], [%1], 16, %2;\n"
                 :: "r"(d), "l"(src), "r"(sz));
}
__device__ __forceinline__ void cpa_commit() {
    asm volatile("cp.async.commit_group;\n" ::: "memory");
}
template <int N>
__device__ __forceinline__ void cpa_wait() {
    asm volatile("cp.async.wait_group %0;\n" :: "n"(N) : "memory");
}

// ---------------- CSR build ----------------
__global__ void zero_cnt_kernel() {
    int i = blockIdx.x * blockDim.x + threadIdx.x;
    if (i < NN) g_cnt[i] = 0;
}

__global__ void hist_kernel(const int* __restrict__ dst) {
    int e = blockIdx.x * blockDim.x + threadIdx.x;
    if (e >= ET) return;
    int d = (e < EE) ? dst[e] : (e - EE);
    atomicAdd(&g_cnt[d], 1);
}

__global__ void scan1_kernel() {
    __shared__ int tmp[1024];
    int t = threadIdx.x;
    int i = blockIdx.x * 1024 + t;
    tmp[t] = (i < NN) ? g_cnt[i] : 0;
    __syncthreads();
    #pragma unroll
    for (int off = 1; off < 1024; off <<= 1) {
        int x = 0;
        if (t >= off) x = tmp[t - off];
        __syncthreads();
        tmp[t] += x;
        __syncthreads();
    }
    if (i < NN) g_scan[i] = tmp[t];
    if (t == 1023) g_bsum[blockIdx.x] = tmp[1023];
}

// Fused scan2 + scan3 + cursor
__global__ void scan23_kernel(int nb) {
    __shared__ int bs[128];
    int t = threadIdx.x;
    if (t < 128) bs[t] = (t < nb) ? g_bsum[t] : 0;
    __syncthreads();
    #pragma unroll
    for (int off = 1; off < 128; off <<= 1) {
        int x = 0;
        if (t < 128 && t >= off) x = bs[t - off];
        __syncthreads();
        if (t < 128) bs[t] += x;
        __syncthreads();
    }
    int i = blockIdx.x * 1024 + t;
    if (i < NN) {
        int blk  = i >> 10;
        int boff = blk ? bs[blk - 1] : 0;
        int inc  = g_scan[i] + boff;
        g_rowptr[i + 1] = inc;
        g_cursor[i]     = inc - g_cnt[i];
        if (i == 0) g_rowptr[0] = 0;
    }
}

__global__ void fill_kernel(const int* __restrict__ src, const int* __restrict__ dst,
                            const float* __restrict__ ew) {
    int e = blockIdx.x * blockDim.x + threadIdx.x;
    if (e >= ET) return;
    int s, d;
    float w;
    if (e < EE) { s = src[e]; d = dst[e]; w = ew[e]; }
    else        { s = d = e - EE; w = 1.0f; }
    int pos = atomicAdd(&g_cursor[d], 1);
    g_edge[pos] = make_int2(s, __float_as_int(w));   // single 8B scattered store
}

// ---------------- W1 -> half2 pairs along k: g_W1h[kw*64+n] = {W1[2kw][n], W1[2kw+1][n]}
__global__ void convw1_kernel(const float* __restrict__ W) {
    int i = blockIdx.x * blockDim.x + threadIdx.x;
    if (i >= (FIN / 2) * HID) return;
    int kw = i >> 6, n = i & 63;
    g_W1h[i] = pkh2(W[(2 * kw) * HID + n], W[(2 * kw + 1) * HID + n]);
}

// ---------------- GEMM1: h1 = x @ W1, [NN,256]@[256,64], fp16 MMA m16n8k16 ----------
// BM=128, BK=16, BN=64. 8 warps: wm 0..3 (32 rows), wn 0..1 (32 cols).
// A: raw fp32 cp.async'd, packed to half2 at fragment load (4 LDS.64 + 4 cvt).
// B: pre-packed half2 from g_W1h. 8 MMAs/tile/warp (was 32 with 2xTF32).
// fp16 mantissa == TF32 mantissa, so A precision is unchanged vs R16; B adds
// ~1.4e-4 RMS element error -> total ~2.6e-4, under the 1e-3 gate.
// Fused epilogue: s1/d1 dot products; h1 stored packed half2.
__global__ __launch_bounds__(256, 3) void gemm1_tc(const float* __restrict__ X,
                                                   const float* __restrict__ A1S,
                                                   const float* __restrict__ A1D) {
    __shared__ float    As[2][128][20];   // fp32, stride 20: conflict-free LDS.64 frags
    __shared__ unsigned Bs[2][8][72];     // half2 words [kword][n], stride 72
    __shared__ float    s_sm[2][128];
    __shared__ float    d_sm[2][128];

    const int t    = threadIdx.x;
    const int lane = t & 31;
    const int w    = t >> 5;
    const int wm   = w >> 1;
    const int wn   = w & 1;
    const int m0   = blockIdx.x * 128;
    const int g    = lane >> 2;           // fragment row/col group
    const int tq   = lane & 3;            // fragment k-quad

    // per-thread load coordinates
    const int ar0 = t >> 2,          ac0 = (t & 3) << 2;          // A chunk 0
    const int ar1 = (t + 256) >> 2,  ac1 = ((t + 256) & 3) << 2;  // A chunk 1
    const int gr0 = m0 + ar0, gr1 = m0 + ar1;
    const bool ok0 = gr0 < NN, ok1 = gr1 < NN;
    const int bro = t >> 4, bco = (t & 15) << 2;                  // B: threads 0..127

    auto load_tile = [&](int tile, int st) {
        int kc = tile * 16;
        cpa16(&As[st][ar0][ac0], X + (size_t)(ok0 ? gr0 : 0) * FIN + kc + ac0, ok0);
        cpa16(&As[st][ar1][ac1], X + (size_t)(ok1 ? gr1 : 0) * FIN + kc + ac1, ok1);
        if (t < 128)
            cpa16(&Bs[st][bro][bco], &g_W1h[(tile * 8 + bro) * 64 + bco], true);
    };

    float acc[2][4][4];
    #pragma unroll
    for (int i = 0; i < 2; i++)
        #pragma unroll
        for (int j = 0; j < 4; j++)
            #pragma unroll
            for (int k = 0; k < 4; k++) acc[i][j][k] = 0.0f;

    load_tile(0, 0);
    cpa_commit();

    int cur = 0;
    for (int tile = 0; tile < 16; tile++) {
        if (tile < 15) {
            load_tile(tile + 1, cur ^ 1);
            cpa_commit();
            cpa_wait<1>();
        } else {
            cpa_wait<0>();
        }
        __syncthreads();

        unsigned bfr[4][2];
        #pragma unroll
        for (int nt = 0; nt < 4; nt++) {
            int n = wn * 32 + nt * 8 + g;
            bfr[nt][0] = Bs[cur][tq][n];
            bfr[nt][1] = Bs[cur][tq + 4][n];
        }
        #pragma unroll
        for (int mt = 0; mt < 2; mt++) {
            int r = wm * 32 + mt * 16 + g;
            float2 v0 = *(float2*)&As[cur][r][2 * tq];
            float2 v1 = *(float2*)&As[cur][r + 8][2 * tq];
            float2 v2 = *(float2*)&As[cur][r][2 * tq + 8];
            float2 v3 = *(float2*)&As[cur][r + 8][2 * tq + 8];
            unsigned afr[4] = { pkh2(v0.x, v0.y), pkh2(v1.x, v1.y),
                                pkh2(v2.x, v2.y), pkh2(v3.x, v3.y) };
            #pragma unroll
            for (int nt = 0; nt < 4; nt++)
                mma_f16(acc[mt][nt], afr, bfr[nt]);
        }
        __syncthreads();
        cur ^= 1;
    }

    // epilogue: store h1 (half2) + fused s/d dot products (from fp32 accs)
    float a_s[8], a_d[8];
    #pragma unroll
    for (int nt = 0; nt < 4; nt++) {
        int c0 = wn * 32 + nt * 8 + tq * 2;
        a_s[nt * 2]     = A1S[c0];
        a_s[nt * 2 + 1] = A1S[c0 + 1];
        a_d[nt * 2]     = A1D[c0];
        a_d[nt * 2 + 1] = A1D[c0 + 1];
    }

    #pragma unroll
    for (int mt = 0; mt < 2; mt++) {
        int r0 = m0 + wm * 32 + mt * 16 + g;
        float sp0 = 0.f, dp0 = 0.f, sp1 = 0.f, dp1 = 0.f;
        #pragma unroll
        for (int nt = 0; nt < 4; nt++) {
            int cp = wn * 16 + nt * 4 + tq;   // half2 column index
            if (r0 < NN)
                g_h1h[(size_t)r0 * 32 + cp] = pkh2(acc[mt][nt][0], acc[mt][nt][1]);
            if (r0 + 8 < NN)
                g_h1h[(size_t)(r0 + 8) * 32 + cp] = pkh2(acc[mt][nt][2], acc[mt][nt][3]);
            sp0 = fmaf(acc[mt][nt][0], a_s[nt * 2],     sp0);
            sp0 = fmaf(acc[mt][nt][1], a_s[nt * 2 + 1], sp0);
            sp1 = fmaf(acc[mt][nt][2], a_s[nt * 2],     sp1);
            sp1 = fmaf(acc[mt][nt][3], a_s[nt * 2 + 1], sp1);
            dp0 = fmaf(acc[mt][nt][0], a_d[nt * 2],     dp0);
            dp0 = fmaf(acc[mt][nt][1], a_d[nt * 2 + 1], dp0);
            dp1 = fmaf(acc[mt][nt][2], a_d[nt * 2],     dp1);
            dp1 = fmaf(acc[mt][nt][3], a_d[nt * 2 + 1], dp1);
        }
        #pragma unroll
        for (int off = 1; off < 4; off <<= 1) {
            sp0 += __shfl_xor_sync(0xffffffffu, sp0, off);
            sp1 += __shfl_xor_sync(0xffffffffu, sp1, off);
            dp0 += __shfl_xor_sync(0xffffffffu, dp0, off);
            dp1 += __shfl_xor_sync(0xffffffffu, dp1, off);
        }
        if (tq == 0) {
            int lr = wm * 32 + mt * 16 + g;
            s_sm[wn][lr]     = sp0;
            s_sm[wn][lr + 8] = sp1;
            d_sm[wn][lr]     = dp0;
            d_sm[wn][lr + 8] = dp1;
        }
    }
    __syncthreads();
    if (t < 128) {
        int gr = m0 + t;
        if (gr < NN) {
            g_s1[gr] = s_sm[0][t] + s_sm[1][t];
            g_d1[gr] = d_sm[0][t] + d_sm[1][t];
        }
    }
}

// ---------------- agg1 + gemm2 fused: warp per dst node ---------------------------
// Gather-softmax aggregation over h1 (D=64), then the warp directly projects its
// relu'd 64-dim row against smem-resident W2 -> h2 (half2) + s2/d2. Eliminates the
// separate gemm2 kernel and the out1 global round-trip. Grid is exactly 12500
// blocks (NN*32/256), so no early returns and __syncthreads is safe.
__global__ __launch_bounds__(256) void agg1_fused(const unsigned* __restrict__ H,
                                                  const float* __restrict__ S,
                                                  const float* __restrict__ DA,
                                                  const float* __restrict__ W2,
                                                  const float* __restrict__ A2S,
                                                  const float* __restrict__ A2D) {
    __shared__ float2 W2s[64][20];     // 10 KB
    __shared__ float  srow[8][64];     // per-warp out1 row
    const int t    = threadIdx.x;
    const int lane = t & 31;
    const int wid  = t >> 5;
    const int v    = (blockIdx.x * 256 + t) >> 5;   // always < NN

    for (int i = t; i < 64 * 20; i += 256) {
        int k = i / 20, j = i % 20;
        W2s[k][j] = *(const float2*)(W2 + k * NC + j * 2);
    }
    __syncthreads();

    int p0 = g_rowptr[v], p1 = g_rowptr[v + 1];
    float dv = DA[v];

    float2 acc = make_float2(0.0f, 0.0f);
    float denom = 0.0f;

    for (int base = p0; base < p1; base += 32) {
        int p = base + lane;
        float wl = 0.0f;
        int   svl = 0;
        if (p < p1) {
            int2 e = g_edge[p];
            svl = e.x;
            float sc = S[svl] + dv;
            sc = sc > 0.0f ? sc : 0.2f * sc;
            float el = __expf(sc);
            denom += el;
            wl = el * __int_as_float(e.y);
        }
        int nj  = p1 - base; if (nj > 32) nj = 32;
        int njp = (nj + 7) & ~7;
        for (int j = 0; j < njp; j += 8) {
            float wb[8]; int sb[8];
            #pragma unroll
            for (int q = 0; q < 8; q++) {
                wb[q] = __shfl_sync(0xffffffffu, wl, j + q);
                sb[q] = __shfl_sync(0xffffffffu, svl, j + q);
            }
            float2 hb[8];
            #pragma unroll
            for (int q = 0; q < 8; q++)
                hb[q] = uph2(H[(size_t)sb[q] * 32 + lane]);
            #pragma unroll
            for (int q = 0; q < 8; q++) {
                acc.x = fmaf(wb[q], hb[q].x, acc.x);
                acc.y = fmaf(wb[q], hb[q].y, acc.y);
            }
        }
    }
    #pragma unroll
    for (int off = 16; off; off >>= 1)
        denom += __shfl_xor_sync(0xffffffffu, denom, off);
    float inv = 1.0f / denom;

    float rx = acc.x * inv, ry = acc.y * inv;
    rx = rx > 0.f ? rx : 0.f;              // relu (layer-1 activation)
    ry = ry > 0.f ? ry : 0.f;
    srow[wid][lane * 2]     = rx;
    srow[wid][lane * 2 + 1] = ry;
    __syncwarp();

    // project: h2 pair per lane (lanes 0..19); lanes 20..31 compute dummies at j=0
    int j = lane < 20 ? lane : 0;
    float hx = 0.f, hy = 0.f;
    #pragma unroll
    for (int k = 0; k < 64; k++) {
        float a = srow[wid][k];
        float2 wv = W2s[k][j];
        hx = fmaf(a, wv.x, hx);
        hy = fmaf(a, wv.y, hy);
    }
    float sp = 0.f, dp = 0.f;
    if (lane < 20) {
        float2 as = *(const float2*)(A2S + j * 2);
        float2 ad = *(const float2*)(A2D + j * 2);
        sp = hx * as.x + hy * as.y;
        dp = hx * ad.x + hy * ad.y;
        g_h2h[(size_t)v * 20 + j] = pkh2(hx, hy);
    }
    #pragma unroll
    for (int off = 16; off; off >>= 1) {
        sp += __shfl_xor_sync(0xffffffffu, sp, off);
        dp += __shfl_xor_sync(0xffffffffu, dp, off);
    }
    if (lane == 0) { g_s2[v] = sp; g_d2[v] = dp; }
}

// ---------------- agg2: warp per dst node, fused pass, MLP=8, half2 H ---------------
__global__ __launch_bounds__(256) void agg2_kernel(const unsigned* __restrict__ H,
                                                   const float* __restrict__ S,
                                                   const float* __restrict__ DA,
                                                   float* __restrict__ OUT) {
    constexpr int DH = NC / 2;   // 20
    int v    = (blockIdx.x * blockDim.x + threadIdx.x) >> 5;
    int lane = threadIdx.x & 31;
    if (v >= NN) return;
    int p0 = g_rowptr[v], p1 = g_rowptr[v + 1];
    float dv = DA[v];

    int cp = lane < DH ? lane : DH - 1;

    float2 acc = make_float2(0.0f, 0.0f);
    float denom = 0.0f;

    for (int base = p0; base < p1; base += 32) {
        int p = base + lane;
        float wl = 0.0f;
        int   svl = 0;
        if (p < p1) {
            int2 e = g_edge[p];
            svl = e.x;
            float sc = S[svl] + dv;
            sc = sc > 0.0f ? sc : 0.2f * sc;
            float el = __expf(sc);
            denom += el;
            wl = el * __int_as_float(e.y);
        }
        int nj  = p1 - base; if (nj > 32) nj = 32;
        int njp = (nj + 7) & ~7;
        for (int j = 0; j < njp; j += 8) {
            float wb[8]; int sb[8];
            #pragma unroll
            for (int q = 0; q < 8; q++) {
                wb[q] = __shfl_sync(0xffffffffu, wl, j + q);
                sb[q] = __shfl_sync(0xffffffffu, svl, j + q);
            }
            float2 hb[8];
            #pragma unroll
            for (int q = 0; q < 8; q++)
                hb[q] = uph2(H[(size_t)sb[q] * DH + cp]);
            #pragma unroll
            for (int q = 0; q < 8; q++) {
                acc.x = fmaf(wb[q], hb[q].x, acc.x);
                acc.y = fmaf(wb[q], hb[q].y, acc.y);
            }
        }
    }
    #pragma unroll
    for (int off = 16; off; off >>= 1)
        denom += __shfl_xor_sync(0xffffffffu, denom, off);
    float inv = 1.0f / denom;

    if (lane < DH)
        *(float2*)(OUT + (size_t)v * NC + lane * 2) =
            make_float2(acc.x * inv, acc.y * inv);
}

// ---------------- launch ----------------
extern "C" void kernel_launch(void* const* d_in, const int* in_sizes, int n_in,
                              void* d_out, int out_size) {
    const float* x   = (const float*)d_in[0];
    const int*   ei  = (const int*)  d_in[1];
    const float* ew  = (const float*)d_in[2];
    const float* W1  = (const float*)d_in[3];
    const float* a1s = (const float*)d_in[4];
    const float* a1d = (const float*)d_in[5];
    const float* W2  = (const float*)d_in[6];
    const float* a2s = (const float*)d_in[7];
    const float* a2d = (const float*)d_in[8];
    float* out = (float*)d_out;

    const int* srcA = ei;
    const int* dstA = ei + EE;

    unsigned *ph1h, *ph2h;
    float *ps1, *pd1, *ps2, *pd2;
    cudaGetSymbolAddress((void**)&ph1h, g_h1h);
    cudaGetSymbolAddress((void**)&ph2h, g_h2h);
    cudaGetSymbolAddress((void**)&ps1,  g_s1);
    cudaGetSymbolAddress((void**)&pd1,  g_d1);
    cudaGetSymbolAddress((void**)&ps2,  g_s2);
    cudaGetSymbolAddress((void**)&pd2,  g_d2);

    // Capture-safe side stream + fork/join events
    static cudaStream_t s2 = nullptr;
    static cudaEvent_t  evF = nullptr, evJ = nullptr;
    if (!s2) {
        cudaStreamCreateWithFlags(&s2, cudaStreamNonBlocking);
        cudaEventCreateWithFlags(&evF, cudaEventDisableTiming);
        cudaEventCreateWithFlags(&evJ, cudaEventDisableTiming);
    }

    const int TPB = 256;
    const int nb  = (NN + 1023) / 1024;

    // Fork: CSR build on side stream; W1 pack + gemm1 on main stream
    cudaEventRecord(evF, 0);
    cudaStreamWaitEvent(s2, evF, 0);
    zero_cnt_kernel<<<(NN + TPB - 1) / TPB, TPB, 0, s2>>>();
    hist_kernel<<<(ET + TPB - 1) / TPB, TPB, 0, s2>>>(dstA);
    scan1_kernel<<<nb, 1024, 0, s2>>>();
    convw1_kernel<<<((FIN / 2) * HID + TPB - 1) / TPB, TPB>>>(W1);   // main, tiny
    gemm1_tc<<<(NN + 127) / 128, 256>>>(x, a1s, a1d);                // main
    scan23_kernel<<<nb, 1024, 0, s2>>>(nb);
    fill_kernel<<<(ET + TPB - 1) / TPB, TPB, 0, s2>>>(srcA, dstA, ew);
    cudaEventRecord(evJ, s2);

    // Join, then the serial tail: fused agg1+gemm2, then agg2
    cudaStreamWaitEvent(0, evJ, 0);
    agg1_fused<<<(NN * 32) / TPB, TPB>>>(ph1h, ps1, pd1, W2, a2s, a2d);
    agg2_kernel<<<(NN * 32 + TPB - 1) / TPB, TPB>>>(ph2h, ps2, pd2, out);
}